// round 8
// baseline (speedup 1.0000x reference)
#include <cuda_runtime.h>
#include <cuda_bf16.h>
#include <cstdint>
#include <cstddef>

// ---------------- problem constants ----------------
#define BATCH 4
#define CDIM  256
#define CIDIM 128
#define NDIM  4096

// ---------------- scratch (device globals) ----------------
__device__ __nv_bfloat16 g_xT_h[BATCH * NDIM * CDIM];   // x^T [b][n][c]
__device__ __nv_bfloat16 g_xT_l[BATCH * NDIM * CDIM];
__device__ __nv_bfloat16 g_W_h[3 * CIDIM * CDIM];       // theta/phi/g weights stacked
__device__ __nv_bfloat16 g_W_l[3 * CIDIM * CDIM];
__device__ __nv_bfloat16 g_OW_h[CDIM * CIDIM];          // out_w
__device__ __nv_bfloat16 g_OW_l[CDIM * CIDIM];
__device__ __nv_bfloat16 g_thT_h[BATCH * NDIM * CIDIM]; // theta^T [b][n][ci]
__device__ __nv_bfloat16 g_thT_l[BATCH * NDIM * CIDIM];
__device__ __nv_bfloat16 g_phT_h[BATCH * NDIM * CIDIM]; // phi^T
__device__ __nv_bfloat16 g_phT_l[BATCH * NDIM * CIDIM];
__device__ __nv_bfloat16 g_gv_h[BATCH * CIDIM * NDIM];  // g [b][ci][m]
__device__ __nv_bfloat16 g_gv_l[BATCH * CIDIM * NDIM];
__device__ float g_scores[(size_t)BATCH * NDIM * NDIM]; // softmax rewrites rows as bf16 hi[4096]|lo[4096]
__device__ __nv_bfloat16 g_midT_h[BATCH * NDIM * CIDIM];
__device__ __nv_bfloat16 g_midT_l[BATCH * NDIM * CIDIM];

// ---------------- helpers ----------------
__device__ __forceinline__ uint32_t smem_u32(const void* p) {
    uint32_t a;
    asm("{ .reg .u64 t; cvta.to.shared.u64 t, %1; cvt.u32.u64 %0, t; }" : "=r"(a) : "l"(p));
    return a;
}
__device__ __forceinline__ void cp16(uint32_t s, const void* g) {
    asm volatile("cp.async.cg.shared.global [%0], [%1], 16;" :: "r"(s), "l"(g));
}
#define CP_COMMIT() asm volatile("cp.async.commit_group;" ::: "memory")

#define LDSM_X4(r, addr) \
    asm volatile("ldmatrix.sync.aligned.m8n8.x4.shared.b16 {%0,%1,%2,%3}, [%4];" \
        : "=r"((r)[0]), "=r"((r)[1]), "=r"((r)[2]), "=r"((r)[3]) : "r"(addr))

#define MMA16816(d, a, b0, b1) \
    asm volatile("mma.sync.aligned.m16n8k16.row.col.f32.bf16.bf16.f32 " \
        "{%0,%1,%2,%3}, {%4,%5,%6,%7}, {%8,%9}, {%0,%1,%2,%3};" \
        : "+f"((d)[0]), "+f"((d)[1]), "+f"((d)[2]), "+f"((d)[3]) \
        : "r"((a)[0]), "r"((a)[1]), "r"((a)[2]), "r"((a)[3]), "r"(b0), "r"(b1))

__device__ __forceinline__ void split_bf16(float v, __nv_bfloat16& h, __nv_bfloat16& l) {
    h = __float2bfloat16(v);
    l = __float2bfloat16(v - __bfloat162float(h));
}
__device__ __forceinline__ uint32_t swz(uint32_t off) { return off ^ ((off >> 3) & 0x70); }

// ---------------- generic 3xBF16 GEMM via mma.sync ----------------
// D[M, N] = sum_k A[m][k] * B[n][k] over 3 passes: (Ah,Bh), (Ah,Bl), (Al,Bh).
// Block tile 128x128, warp tile 64x32 (8 warps: 2 M x 4 N), K-chunk 64, double-buffered cp.async.
// MODE 0: bf16 hi/lo pair store [m*ldo+n] + bias[n]      (theta^T / phi^T)
// MODE 1: bf16 hi/lo pair store [m*ldo+n] + bias[m]      (g)
// MODE 2: fp32 store [m*ldo+n]                            (scores)
// MODE 3: bf16 hi/lo pair store [m*ldo+n], no bias        (mid^T)
// MODE 4: fp32 store + bias[m] + resid[m*ldo+n]           (final out)
template<int MODE>
__global__ __launch_bounds__(256)
void mma_gemm(const __nv_bfloat16* __restrict__ Ah, const __nv_bfloat16* __restrict__ Al,
              long sA, int lda,
              const __nv_bfloat16* __restrict__ Bh, const __nv_bfloat16* __restrict__ Bl,
              long sB, int ldb,
              int K,
              float* __restrict__ outf,
              __nv_bfloat16* __restrict__ outh, __nv_bfloat16* __restrict__ outl,
              long sO, int ldo,
              const float* __restrict__ bias,
              const float* __restrict__ resid, long sR)
{
    extern __shared__ char dsm[];
    const uint32_t smem = (smem_u32(dsm) + 1023u) & ~1023u;
    const int STG = 32768;  // 16KB A + 16KB B per stage

    const int tid  = threadIdx.x;
    const int wid  = tid >> 5;
    const int lane = tid & 31;
    const int wm   = wid >> 2;     // 0..1  (M)
    const int wn   = wid & 3;      // 0..3  (N)

    const int bz = blockIdx.z;
    const int m0 = blockIdx.y * 128;
    const int n0 = blockIdx.x * 128;
    Ah += (size_t)bz * sA;  Al += (size_t)bz * sA;
    Bh += (size_t)bz * sB;  Bl += (size_t)bz * sB;

    const int kc64 = K / 64;
    const int nch  = 3 * kc64;

    // per-thread load coords (A and B tiles both 128 rows x 128B)
    const int lrow = tid >> 3;
    const int lc16 = tid & 7;

    float acc[4][4][4];
#pragma unroll
    for (int i = 0; i < 4; i++)
#pragma unroll
        for (int j = 0; j < 4; j++)
#pragma unroll
            for (int r = 0; r < 4; r++) acc[i][j][r] = 0.f;

    auto load_chunk = [&](int c) {
        const int p  = c / kc64;
        const int k0 = (c % kc64) * 64;
        const __nv_bfloat16* Aop = (p < 2) ? Ah : Al;
        const __nv_bfloat16* Bop = (p == 1) ? Bl : Bh;
        const uint32_t sb = smem + (c & 1) * STG;
#pragma unroll
        for (int it = 0; it < 4; it++) {
            int row = lrow + it * 32;
            uint32_t off = swz(row * 128 + lc16 * 16);
            cp16(sb + off, Aop + (size_t)(m0 + row) * lda + k0 + lc16 * 8);
        }
#pragma unroll
        for (int it = 0; it < 4; it++) {
            int row = lrow + it * 32;
            uint32_t off = swz(row * 128 + lc16 * 16);
            cp16(sb + 16384 + off, Bop + (size_t)(n0 + row) * ldb + k0 + lc16 * 8);
        }
        CP_COMMIT();
    };

    // fragment load coords
    const int rA  = wm * 64 + (lane & 15);
    const int cA  = lane >> 4;                           // 16B half
    const int rB  = wn * 32 + (lane & 7) + ((lane >> 4) << 3);
    const int cB  = (lane >> 3) & 1;

    load_chunk(0);
    for (int c = 0; c < nch; c++) {
        if (c + 1 < nch) {
            load_chunk(c + 1);
            asm volatile("cp.async.wait_group 1;" ::: "memory");
        } else {
            asm volatile("cp.async.wait_group 0;" ::: "memory");
        }
        __syncthreads();
        const uint32_t sAb = smem + (c & 1) * STG;
        const uint32_t sBb = sAb + 16384;
#pragma unroll
        for (int k16 = 0; k16 < 4; k16++) {
            uint32_t a[4][4];
#pragma unroll
            for (int mi = 0; mi < 4; mi++) {
                uint32_t off = swz((rA + mi * 16) * 128 + (k16 * 2 + cA) * 16);
                LDSM_X4(a[mi], sAb + off);
            }
            uint32_t bf[2][4];
#pragma unroll
            for (int njp = 0; njp < 2; njp++) {
                uint32_t off = swz((rB + njp * 16) * 128 + (k16 * 2 + cB) * 16);
                LDSM_X4(bf[njp], sBb + off);
            }
#pragma unroll
            for (int mi = 0; mi < 4; mi++)
#pragma unroll
                for (int nj = 0; nj < 4; nj++)
                    MMA16816(acc[mi][nj], a[mi], bf[nj >> 1][(nj & 1) * 2], bf[nj >> 1][(nj & 1) * 2 + 1]);
        }
        __syncthreads();
    }

    // ---- epilogue ----
    const int mb = m0 + wm * 64 + (lane >> 2);
    const int nb = n0 + wn * 32 + (lane & 3) * 2;
#pragma unroll
    for (int mi = 0; mi < 4; mi++) {
#pragma unroll
        for (int half = 0; half < 2; half++) {
            const int m = mb + mi * 16 + half * 8;
            float bvr = 0.f;
            if (MODE == 1 || MODE == 4) bvr = bias[m];
#pragma unroll
            for (int nj = 0; nj < 4; nj++) {
                const int n = nb + nj * 8;
                float v0 = acc[mi][nj][half * 2 + 0];
                float v1 = acc[mi][nj][half * 2 + 1];
                if (MODE == 0) { v0 += bias[n]; v1 += bias[n + 1]; }
                if (MODE == 1 || MODE == 4) { v0 += bvr; v1 += bvr; }
                const size_t addr = (size_t)bz * sO + (size_t)m * ldo + n;
                if (MODE == 2 || MODE == 4) {
                    if (MODE == 4) {
                        float2 xv = *(const float2*)&resid[(size_t)bz * sR + (size_t)m * ldo + n];
                        v0 += xv.x; v1 += xv.y;
                    }
                    float2 f; f.x = v0; f.y = v1;
                    *(float2*)&outf[addr] = f;
                } else {
                    __nv_bfloat16 h0, l0, h1, l1;
                    split_bf16(v0, h0, l0);
                    split_bf16(v1, h1, l1);
                    __nv_bfloat162 hh; hh.x = h0; hh.y = h1;
                    __nv_bfloat162 ll; ll.x = l0; ll.y = l1;
                    *(__nv_bfloat162*)&outh[addr] = hh;
                    *(__nv_bfloat162*)&outl[addr] = ll;
                }
            }
        }
    }
}

// ---------------- softmax (in-place fp32 -> bf16 hi/lo) ----------------
__global__ __launch_bounds__(256)
void softmax_k(float* __restrict__ S)
{
    float* rowf = S + (size_t)blockIdx.x * NDIM;
    __nv_bfloat16* rowh = (__nv_bfloat16*)rowf;
    __nv_bfloat16* rowl = rowh + NDIM;
    const int t = threadIdx.x;
    float v[16];
    float mx = -3.402823466e+38f;
#pragma unroll
    for (int i = 0; i < 16; i++) {
        v[i] = rowf[t + i * 256];
        mx = fmaxf(mx, v[i]);
    }
    __shared__ float redm[8];
    __shared__ float reds[8];
#pragma unroll
    for (int o = 16; o > 0; o >>= 1) mx = fmaxf(mx, __shfl_xor_sync(0xFFFFFFFFu, mx, o));
    if ((t & 31) == 0) redm[t >> 5] = mx;
    __syncthreads();
    mx = redm[0];
#pragma unroll
    for (int w = 1; w < 8; w++) mx = fmaxf(mx, redm[w]);
    float s = 0.f;
#pragma unroll
    for (int i = 0; i < 16; i++) { v[i] = __expf(v[i] - mx); s += v[i]; }
#pragma unroll
    for (int o = 16; o > 0; o >>= 1) s += __shfl_xor_sync(0xFFFFFFFFu, s, o);
    if ((t & 31) == 0) reds[t >> 5] = s;
    __syncthreads();
    s = reds[0];
#pragma unroll
    for (int w = 1; w < 8; w++) s += reds[w];
    const float inv = 1.f / s;
    __syncthreads();   // all reads of rowf done before bf16 overwrite
#pragma unroll
    for (int i = 0; i < 16; i++) {
        int col = t + i * 256;
        __nv_bfloat16 h, l;
        split_bf16(v[i] * inv, h, l);
        rowh[col] = h;
        rowl[col] = l;
    }
}

// ---------------- prep kernels ----------------
__global__ void split_arr_k(const float* __restrict__ src,
                            __nv_bfloat16* __restrict__ h, __nv_bfloat16* __restrict__ l, int n)
{
    int i = blockIdx.x * 256 + threadIdx.x;
    if (i < n) {
        __nv_bfloat16 hh, ll; split_bf16(src[i], hh, ll);
        h[i] = hh; l[i] = ll;
    }
}

__global__ void xT_split_k(const float* __restrict__ x,
                           __nv_bfloat16* __restrict__ th, __nv_bfloat16* __restrict__ tl)
{
    __shared__ float t[32][33];
    const int b = blockIdx.z;
    const int n0 = blockIdx.x * 32, c0 = blockIdx.y * 32;
    const int tx = threadIdx.x, ty = threadIdx.y;
    const float* xb = x + (size_t)b * CDIM * NDIM;
#pragma unroll
    for (int i = 0; i < 32; i += 8)
        t[ty + i][tx] = xb[(size_t)(c0 + ty + i) * NDIM + n0 + tx];
    __syncthreads();
    __nv_bfloat16* oh = th + (size_t)b * NDIM * CDIM;
    __nv_bfloat16* ol = tl + (size_t)b * NDIM * CDIM;
#pragma unroll
    for (int i = 0; i < 32; i += 8) {
        __nv_bfloat16 h, l; split_bf16(t[tx][ty + i], h, l);
        size_t a = (size_t)(n0 + ty + i) * CDIM + c0 + tx;
        oh[a] = h; ol[a] = l;
    }
}

// ---------------- launch ----------------
extern "C" void kernel_launch(void* const* d_in, const int* in_sizes, int n_in,
                              void* d_out, int out_size)
{
    const float* x       = (const float*)d_in[0];
    const float* theta_w = (const float*)d_in[1];
    const float* theta_b = (const float*)d_in[2];
    const float* phi_w   = (const float*)d_in[3];
    const float* phi_b   = (const float*)d_in[4];
    const float* g_w     = (const float*)d_in[5];
    const float* g_b     = (const float*)d_in[6];
    const float* out_w   = (const float*)d_in[7];
    const float* out_b   = (const float*)d_in[8];
    float* out = (float*)d_out;

    __nv_bfloat16 *xTh, *xTl, *Wh, *Wl, *OWh, *OWl;
    __nv_bfloat16 *thTh, *thTl, *phTh, *phTl, *gvh, *gvl, *mTh, *mTl;
    float* scores;
    cudaGetSymbolAddress((void**)&xTh,  g_xT_h);  cudaGetSymbolAddress((void**)&xTl,  g_xT_l);
    cudaGetSymbolAddress((void**)&Wh,   g_W_h);   cudaGetSymbolAddress((void**)&Wl,   g_W_l);
    cudaGetSymbolAddress((void**)&OWh,  g_OW_h);  cudaGetSymbolAddress((void**)&OWl,  g_OW_l);
    cudaGetSymbolAddress((void**)&thTh, g_thT_h); cudaGetSymbolAddress((void**)&thTl, g_thT_l);
    cudaGetSymbolAddress((void**)&phTh, g_phT_h); cudaGetSymbolAddress((void**)&phTl, g_phT_l);
    cudaGetSymbolAddress((void**)&gvh,  g_gv_h);  cudaGetSymbolAddress((void**)&gvl,  g_gv_l);
    cudaGetSymbolAddress((void**)&mTh,  g_midT_h);cudaGetSymbolAddress((void**)&mTl,  g_midT_l);
    cudaGetSymbolAddress((void**)&scores, g_scores);

    const int SM = 1024 + 2 * 32768;   // 66560
    cudaFuncSetAttribute(mma_gemm<0>, cudaFuncAttributeMaxDynamicSharedMemorySize, SM);
    cudaFuncSetAttribute(mma_gemm<1>, cudaFuncAttributeMaxDynamicSharedMemorySize, SM);
    cudaFuncSetAttribute(mma_gemm<2>, cudaFuncAttributeMaxDynamicSharedMemorySize, SM);
    cudaFuncSetAttribute(mma_gemm<3>, cudaFuncAttributeMaxDynamicSharedMemorySize, SM);
    cudaFuncSetAttribute(mma_gemm<4>, cudaFuncAttributeMaxDynamicSharedMemorySize, SM);

    // prep: split weights + transpose/split x
    const int NW = CIDIM * CDIM; // 32768
    split_arr_k<<<(NW + 255) / 256, 256>>>(theta_w, Wh,          Wl,          NW);
    split_arr_k<<<(NW + 255) / 256, 256>>>(phi_w,   Wh + NW,     Wl + NW,     NW);
    split_arr_k<<<(NW + 255) / 256, 256>>>(g_w,     Wh + 2 * NW, Wl + 2 * NW, NW);
    split_arr_k<<<(NW + 255) / 256, 256>>>(out_w,   OWh,         OWl,         NW);
    xT_split_k<<<dim3(NDIM / 32, CDIM / 32, BATCH), dim3(32, 8)>>>(x, xTh, xTl);

    const long sXT = (long)NDIM * CDIM;
    const long sP  = (long)NDIM * CIDIM;   // theta^T / phi^T / mid^T batch stride
    const long sG  = (long)CIDIM * NDIM;
    const long sS  = (long)NDIM * NDIM;    // scores fp32 batch stride
    const long sX  = (long)CDIM * NDIM;
    dim3 blk(256);

    // 1) theta^T / phi^T: D[n][ci] = xT[n,:] . W[ci,:] + bias[ci]   (M=4096, N=128, K=256)
    mma_gemm<0><<<dim3(1, 32, BATCH), blk, SM>>>(
        xTh, xTl, sXT, CDIM, Wh, Wl, 0, CDIM, CDIM,
        nullptr, thTh, thTl, sP, CIDIM, theta_b, nullptr, 0);
    mma_gemm<0><<<dim3(1, 32, BATCH), blk, SM>>>(
        xTh, xTl, sXT, CDIM, Wh + NW, Wl + NW, 0, CDIM, CDIM,
        nullptr, phTh, phTl, sP, CIDIM, phi_b, nullptr, 0);

    // 2) g: D[ci][m] = W[ci,:] . xT[m,:] + bias[ci]                 (M=128, N=4096, K=256)
    mma_gemm<1><<<dim3(32, 1, BATCH), blk, SM>>>(
        Wh + 2 * NW, Wl + 2 * NW, 0, CDIM, xTh, xTl, sXT, CDIM, CDIM,
        nullptr, gvh, gvl, sG, NDIM, g_b, nullptr, 0);

    // 3) scores: S[n][m] = thT[n,:] . phT[m,:]                      (M=4096, N=4096, K=128)
    mma_gemm<2><<<dim3(32, 32, BATCH), blk, SM>>>(
        thTh, thTl, sP, CIDIM, phTh, phTl, sP, CIDIM, CIDIM,
        scores, nullptr, nullptr, sS, NDIM, nullptr, nullptr, 0);

    // 4) softmax rows -> P hi/lo bf16 in place
    softmax_k<<<BATCH * NDIM, 256>>>(scores);

    // 5) aggregation: midT[n][ci] = P[n,:] . g[ci,:]                (M=4096, N=128, K=4096)
    __nv_bfloat16* Ph = (__nv_bfloat16*)scores;   // row stride 8192 bf16 elems
    __nv_bfloat16* Pl = Ph + NDIM;
    mma_gemm<3><<<dim3(1, 32, BATCH), blk, SM>>>(
        Ph, Pl, (long)NDIM * 2 * NDIM, 2 * NDIM, gvh, gvl, sG, NDIM, NDIM,
        nullptr, mTh, mTl, sP, CIDIM, nullptr, nullptr, 0);

    // 6) final: out[c][n] = OW[c,:] . midT[n,:] + out_b[c] + x[c][n]  (M=256, N=4096, K=128)
    mma_gemm<4><<<dim3(32, 2, BATCH), blk, SM>>>(
        OWh, OWl, 0, CIDIM, mTh, mTl, sP, CIDIM, CIDIM,
        out, nullptr, nullptr, sX, NDIM, out_b, x, sX);
}

// round 9
// speedup vs baseline: 1.0047x; 1.0047x over previous
#include <cuda_runtime.h>
#include <cuda_bf16.h>
#include <cstdint>
#include <cstddef>

// ---------------- problem constants ----------------
#define BATCH 4
#define CDIM  256
#define CIDIM 128
#define NDIM  4096

// ---------------- scratch (device globals) ----------------
__device__ __nv_bfloat16 g_xT_h[BATCH * NDIM * CDIM];   // x^T [b][n][c]
__device__ __nv_bfloat16 g_xT_l[BATCH * NDIM * CDIM];
__device__ __nv_bfloat16 g_W_h[3 * CIDIM * CDIM];       // theta/phi/g weights stacked
__device__ __nv_bfloat16 g_W_l[3 * CIDIM * CDIM];
__device__ __nv_bfloat16 g_OW_h[CDIM * CIDIM];          // out_w
__device__ __nv_bfloat16 g_OW_l[CDIM * CIDIM];
__device__ __nv_bfloat16 g_thT_h[BATCH * NDIM * CIDIM]; // theta^T [b][n][ci]
__device__ __nv_bfloat16 g_thT_l[BATCH * NDIM * CIDIM];
__device__ __nv_bfloat16 g_phT_h[BATCH * NDIM * CIDIM]; // phi^T
__device__ __nv_bfloat16 g_phT_l[BATCH * NDIM * CIDIM];
__device__ __nv_bfloat16 g_gv_h[BATCH * CIDIM * NDIM];  // g [b][ci][m]
__device__ __nv_bfloat16 g_gv_l[BATCH * CIDIM * NDIM];
__device__ float g_scores[(size_t)BATCH * NDIM * NDIM]; // softmax rewrites rows as bf16 hi[4096]|lo[4096]
__device__ __nv_bfloat16 g_midT_h[BATCH * NDIM * CIDIM];
__device__ __nv_bfloat16 g_midT_l[BATCH * NDIM * CIDIM];

// ---------------- helpers ----------------
__device__ __forceinline__ uint32_t smem_u32(const void* p) {
    uint32_t a;
    asm("{ .reg .u64 t; cvta.to.shared.u64 t, %1; cvt.u32.u64 %0, t; }" : "=r"(a) : "l"(p));
    return a;
}
__device__ __forceinline__ void cp16(uint32_t s, const void* g) {
    asm volatile("cp.async.cg.shared.global [%0], [%1], 16;" :: "r"(s), "l"(g));
}
#define CP_COMMIT() asm volatile("cp.async.commit_group;" ::: "memory")

#define LDSM_X4(r, addr) \
    asm volatile("ldmatrix.sync.aligned.m8n8.x4.shared.b16 {%0,%1,%2,%3}, [%4];" \
        : "=r"((r)[0]), "=r"((r)[1]), "=r"((r)[2]), "=r"((r)[3]) : "r"(addr))

#define MMA16816(d, a, b0, b1) \
    asm volatile("mma.sync.aligned.m16n8k16.row.col.f32.bf16.bf16.f32 " \
        "{%0,%1,%2,%3}, {%4,%5,%6,%7}, {%8,%9}, {%0,%1,%2,%3};" \
        : "+f"((d)[0]), "+f"((d)[1]), "+f"((d)[2]), "+f"((d)[3]) \
        : "r"((a)[0]), "r"((a)[1]), "r"((a)[2]), "r"((a)[3]), "r"(b0), "r"(b1))

__device__ __forceinline__ void split_bf16(float v, __nv_bfloat16& h, __nv_bfloat16& l) {
    h = __float2bfloat16(v);
    l = __float2bfloat16(v - __bfloat162float(h));
}
__device__ __forceinline__ uint32_t swz(uint32_t off) { return off ^ ((off >> 3) & 0x70); }

// ---------------- generic 3xBF16 GEMM via mma.sync ----------------
// D[M, N] = sum_k A[m][k] * B[n][k] over 3 passes: (Ah,Bh), (Ah,Bl), (Al,Bh).
// Block tile 128x128, warp tile 64x32 (8 warps: 2 M x 4 N), K-chunk 64, double-buffered cp.async.
// MODE 0: bf16 hi/lo pair store [m*ldo+n] + bias[n]      (theta^T / phi^T)
// MODE 1: bf16 hi/lo pair store [m*ldo+n] + bias[m]      (g)
// MODE 2: fp32 store [m*ldo+n]                            (scores)
// MODE 3: bf16 hi/lo pair store [m*ldo+n], no bias        (mid^T)
// MODE 4: fp32 store + bias[m] + resid[m*ldo+n]           (final out)
template<int MODE>
__global__ __launch_bounds__(256)
void mma_gemm(const __nv_bfloat16* __restrict__ Ah, const __nv_bfloat16* __restrict__ Al,
              long sA, int lda,
              const __nv_bfloat16* __restrict__ Bh, const __nv_bfloat16* __restrict__ Bl,
              long sB, int ldb,
              int K,
              float* __restrict__ outf,
              __nv_bfloat16* __restrict__ outh, __nv_bfloat16* __restrict__ outl,
              long sO, int ldo,
              const float* __restrict__ bias,
              const float* __restrict__ resid, long sR)
{
    extern __shared__ char dsm[];
    const uint32_t smem = (smem_u32(dsm) + 1023u) & ~1023u;
    const int STG = 32768;  // 16KB A + 16KB B per stage

    const int tid  = threadIdx.x;
    const int wid  = tid >> 5;
    const int lane = tid & 31;
    const int wm   = wid >> 2;     // 0..1  (M)
    const int wn   = wid & 3;      // 0..3  (N)

    const int bz = blockIdx.z;
    const int m0 = blockIdx.y * 128;
    const int n0 = blockIdx.x * 128;
    Ah += (size_t)bz * sA;  Al += (size_t)bz * sA;
    Bh += (size_t)bz * sB;  Bl += (size_t)bz * sB;

    const int kc64 = K / 64;
    const int nch  = 3 * kc64;

    // per-thread load coords (A and B tiles both 128 rows x 128B)
    const int lrow = tid >> 3;
    const int lc16 = tid & 7;

    float acc[4][4][4];
#pragma unroll
    for (int i = 0; i < 4; i++)
#pragma unroll
        for (int j = 0; j < 4; j++)
#pragma unroll
            for (int r = 0; r < 4; r++) acc[i][j][r] = 0.f;

    auto load_chunk = [&](int c) {
        const int p  = c / kc64;
        const int k0 = (c % kc64) * 64;
        const __nv_bfloat16* Aop = (p < 2) ? Ah : Al;
        const __nv_bfloat16* Bop = (p == 1) ? Bl : Bh;
        const uint32_t sb = smem + (c & 1) * STG;
#pragma unroll
        for (int it = 0; it < 4; it++) {
            int row = lrow + it * 32;
            uint32_t off = swz(row * 128 + lc16 * 16);
            cp16(sb + off, Aop + (size_t)(m0 + row) * lda + k0 + lc16 * 8);
        }
#pragma unroll
        for (int it = 0; it < 4; it++) {
            int row = lrow + it * 32;
            uint32_t off = swz(row * 128 + lc16 * 16);
            cp16(sb + 16384 + off, Bop + (size_t)(n0 + row) * ldb + k0 + lc16 * 8);
        }
        CP_COMMIT();
    };

    // fragment load coords
    const int rA  = wm * 64 + (lane & 15);
    const int cA  = lane >> 4;                           // 16B half
    const int rB  = wn * 32 + (lane & 7) + ((lane >> 4) << 3);
    const int cB  = (lane >> 3) & 1;

    load_chunk(0);
    for (int c = 0; c < nch; c++) {
        if (c + 1 < nch) {
            load_chunk(c + 1);
            asm volatile("cp.async.wait_group 1;" ::: "memory");
        } else {
            asm volatile("cp.async.wait_group 0;" ::: "memory");
        }
        __syncthreads();
        const uint32_t sAb = smem + (c & 1) * STG;
        const uint32_t sBb = sAb + 16384;
#pragma unroll
        for (int k16 = 0; k16 < 4; k16++) {
            uint32_t a[4][4];
#pragma unroll
            for (int mi = 0; mi < 4; mi++) {
                uint32_t off = swz((rA + mi * 16) * 128 + (k16 * 2 + cA) * 16);
                LDSM_X4(a[mi], sAb + off);
            }
            uint32_t bf[2][4];
#pragma unroll
            for (int njp = 0; njp < 2; njp++) {
                uint32_t off = swz((rB + njp * 16) * 128 + (k16 * 2 + cB) * 16);
                LDSM_X4(bf[njp], sBb + off);
            }
#pragma unroll
            for (int mi = 0; mi < 4; mi++)
#pragma unroll
                for (int nj = 0; nj < 4; nj++)
                    MMA16816(acc[mi][nj], a[mi], bf[nj >> 1][(nj & 1) * 2], bf[nj >> 1][(nj & 1) * 2 + 1]);
        }
        __syncthreads();
    }

    // ---- epilogue ----
    const int mb = m0 + wm * 64 + (lane >> 2);
    const int nb = n0 + wn * 32 + (lane & 3) * 2;
#pragma unroll
    for (int mi = 0; mi < 4; mi++) {
#pragma unroll
        for (int half = 0; half < 2; half++) {
            const int m = mb + mi * 16 + half * 8;
            float bvr = 0.f;
            if (MODE == 1 || MODE == 4) bvr = bias[m];
#pragma unroll
            for (int nj = 0; nj < 4; nj++) {
                const int n = nb + nj * 8;
                float v0 = acc[mi][nj][half * 2 + 0];
                float v1 = acc[mi][nj][half * 2 + 1];
                if (MODE == 0) { v0 += bias[n]; v1 += bias[n + 1]; }
                if (MODE == 1 || MODE == 4) { v0 += bvr; v1 += bvr; }
                const size_t addr = (size_t)bz * sO + (size_t)m * ldo + n;
                if (MODE == 2 || MODE == 4) {
                    if (MODE == 4) {
                        float2 xv = *(const float2*)&resid[(size_t)bz * sR + (size_t)m * ldo + n];
                        v0 += xv.x; v1 += xv.y;
                    }
                    float2 f; f.x = v0; f.y = v1;
                    *(float2*)&outf[addr] = f;
                } else {
                    __nv_bfloat16 h0, l0, h1, l1;
                    split_bf16(v0, h0, l0);
                    split_bf16(v1, h1, l1);
                    __nv_bfloat162 hh; hh.x = h0; hh.y = h1;
                    __nv_bfloat162 ll; ll.x = l0; ll.y = l1;
                    *(__nv_bfloat162*)&outh[addr] = hh;
                    *(__nv_bfloat162*)&outl[addr] = ll;
                }
            }
        }
    }
}

// ---------------- softmax (in-place fp32 -> bf16 hi/lo) ----------------
__global__ __launch_bounds__(256)
void softmax_k(float* __restrict__ S)
{
    float* rowf = S + (size_t)blockIdx.x * NDIM;
    __nv_bfloat16* rowh = (__nv_bfloat16*)rowf;
    __nv_bfloat16* rowl = rowh + NDIM;
    const int t = threadIdx.x;
    float v[16];
    float mx = -3.402823466e+38f;
#pragma unroll
    for (int i = 0; i < 16; i++) {
        v[i] = rowf[t + i * 256];
        mx = fmaxf(mx, v[i]);
    }
    __shared__ float redm[8];
    __shared__ float reds[8];
#pragma unroll
    for (int o = 16; o > 0; o >>= 1) mx = fmaxf(mx, __shfl_xor_sync(0xFFFFFFFFu, mx, o));
    if ((t & 31) == 0) redm[t >> 5] = mx;
    __syncthreads();
    mx = redm[0];
#pragma unroll
    for (int w = 1; w < 8; w++) mx = fmaxf(mx, redm[w]);
    float s = 0.f;
#pragma unroll
    for (int i = 0; i < 16; i++) { v[i] = __expf(v[i] - mx); s += v[i]; }
#pragma unroll
    for (int o = 16; o > 0; o >>= 1) s += __shfl_xor_sync(0xFFFFFFFFu, s, o);
    if ((t & 31) == 0) reds[t >> 5] = s;
    __syncthreads();
    s = reds[0];
#pragma unroll
    for (int w = 1; w < 8; w++) s += reds[w];
    const float inv = 1.f / s;
    __syncthreads();   // all reads of rowf done before bf16 overwrite
#pragma unroll
    for (int i = 0; i < 16; i++) {
        int col = t + i * 256;
        __nv_bfloat16 h, l;
        split_bf16(v[i] * inv, h, l);
        rowh[col] = h;
        rowl[col] = l;
    }
}

// ---------------- prep kernels ----------------
__global__ void split_arr_k(const float* __restrict__ src,
                            __nv_bfloat16* __restrict__ h, __nv_bfloat16* __restrict__ l, int n)
{
    int i = blockIdx.x * 256 + threadIdx.x;
    if (i < n) {
        __nv_bfloat16 hh, ll; split_bf16(src[i], hh, ll);
        h[i] = hh; l[i] = ll;
    }
}

__global__ void xT_split_k(const float* __restrict__ x,
                           __nv_bfloat16* __restrict__ th, __nv_bfloat16* __restrict__ tl)
{
    __shared__ float t[32][33];
    const int b = blockIdx.z;
    const int n0 = blockIdx.x * 32, c0 = blockIdx.y * 32;
    const int tx = threadIdx.x, ty = threadIdx.y;
    const float* xb = x + (size_t)b * CDIM * NDIM;
#pragma unroll
    for (int i = 0; i < 32; i += 8)
        t[ty + i][tx] = xb[(size_t)(c0 + ty + i) * NDIM + n0 + tx];
    __syncthreads();
    __nv_bfloat16* oh = th + (size_t)b * NDIM * CDIM;
    __nv_bfloat16* ol = tl + (size_t)b * NDIM * CDIM;
#pragma unroll
    for (int i = 0; i < 32; i += 8) {
        __nv_bfloat16 h, l; split_bf16(t[tx][ty + i], h, l);
        size_t a = (size_t)(n0 + ty + i) * CDIM + c0 + tx;
        oh[a] = h; ol[a] = l;
    }
}

// ---------------- launch ----------------
extern "C" void kernel_launch(void* const* d_in, const int* in_sizes, int n_in,
                              void* d_out, int out_size)
{
    const float* x       = (const float*)d_in[0];
    const float* theta_w = (const float*)d_in[1];
    const float* theta_b = (const float*)d_in[2];
    const float* phi_w   = (const float*)d_in[3];
    const float* phi_b   = (const float*)d_in[4];
    const float* g_w     = (const float*)d_in[5];
    const float* g_b     = (const float*)d_in[6];
    const float* out_w   = (const float*)d_in[7];
    const float* out_b   = (const float*)d_in[8];
    float* out = (float*)d_out;

    __nv_bfloat16 *xTh, *xTl, *Wh, *Wl, *OWh, *OWl;
    __nv_bfloat16 *thTh, *thTl, *phTh, *phTl, *gvh, *gvl, *mTh, *mTl;
    float* scores;
    cudaGetSymbolAddress((void**)&xTh,  g_xT_h);  cudaGetSymbolAddress((void**)&xTl,  g_xT_l);
    cudaGetSymbolAddress((void**)&Wh,   g_W_h);   cudaGetSymbolAddress((void**)&Wl,   g_W_l);
    cudaGetSymbolAddress((void**)&OWh,  g_OW_h);  cudaGetSymbolAddress((void**)&OWl,  g_OW_l);
    cudaGetSymbolAddress((void**)&thTh, g_thT_h); cudaGetSymbolAddress((void**)&thTl, g_thT_l);
    cudaGetSymbolAddress((void**)&phTh, g_phT_h); cudaGetSymbolAddress((void**)&phTl, g_phT_l);
    cudaGetSymbolAddress((void**)&gvh,  g_gv_h);  cudaGetSymbolAddress((void**)&gvl,  g_gv_l);
    cudaGetSymbolAddress((void**)&mTh,  g_midT_h);cudaGetSymbolAddress((void**)&mTl,  g_midT_l);
    cudaGetSymbolAddress((void**)&scores, g_scores);

    const int SM = 1024 + 2 * 32768;   // 66560
    cudaFuncSetAttribute(mma_gemm<0>, cudaFuncAttributeMaxDynamicSharedMemorySize, SM);
    cudaFuncSetAttribute(mma_gemm<1>, cudaFuncAttributeMaxDynamicSharedMemorySize, SM);
    cudaFuncSetAttribute(mma_gemm<2>, cudaFuncAttributeMaxDynamicSharedMemorySize, SM);
    cudaFuncSetAttribute(mma_gemm<3>, cudaFuncAttributeMaxDynamicSharedMemorySize, SM);
    cudaFuncSetAttribute(mma_gemm<4>, cudaFuncAttributeMaxDynamicSharedMemorySize, SM);

    // prep: split weights + transpose/split x
    const int NW = CIDIM * CDIM; // 32768
    split_arr_k<<<(NW + 255) / 256, 256>>>(theta_w, Wh,          Wl,          NW);
    split_arr_k<<<(NW + 255) / 256, 256>>>(phi_w,   Wh + NW,     Wl + NW,     NW);
    split_arr_k<<<(NW + 255) / 256, 256>>>(g_w,     Wh + 2 * NW, Wl + 2 * NW, NW);
    split_arr_k<<<(NW + 255) / 256, 256>>>(out_w,   OWh,         OWl,         NW);
    xT_split_k<<<dim3(NDIM / 32, CDIM / 32, BATCH), dim3(32, 8)>>>(x, xTh, xTl);

    const long sXT = (long)NDIM * CDIM;
    const long sP  = (long)NDIM * CIDIM;   // theta^T / phi^T / mid^T batch stride
    const long sG  = (long)CIDIM * NDIM;
    const long sS  = (long)NDIM * NDIM;    // scores fp32 batch stride
    const long sX  = (long)CDIM * NDIM;
    dim3 blk(256);

    // 1) theta^T / phi^T: D[n][ci] = xT[n,:] . W[ci,:] + bias[ci]   (M=4096, N=128, K=256)
    mma_gemm<0><<<dim3(1, 32, BATCH), blk, SM>>>(
        xTh, xTl, sXT, CDIM, Wh, Wl, 0, CDIM, CDIM,
        nullptr, thTh, thTl, sP, CIDIM, theta_b, nullptr, 0);
    mma_gemm<0><<<dim3(1, 32, BATCH), blk, SM>>>(
        xTh, xTl, sXT, CDIM, Wh + NW, Wl + NW, 0, CDIM, CDIM,
        nullptr, phTh, phTl, sP, CIDIM, phi_b, nullptr, 0);

    // 2) g: D[ci][m] = W[ci,:] . xT[m,:] + bias[ci]                 (M=128, N=4096, K=256)
    mma_gemm<1><<<dim3(32, 1, BATCH), blk, SM>>>(
        Wh + 2 * NW, Wl + 2 * NW, 0, CDIM, xTh, xTl, sXT, CDIM, CDIM,
        nullptr, gvh, gvl, sG, NDIM, g_b, nullptr, 0);

    // 3) scores: S[n][m] = thT[n,:] . phT[m,:]                      (M=4096, N=4096, K=128)
    mma_gemm<2><<<dim3(32, 32, BATCH), blk, SM>>>(
        thTh, thTl, sP, CIDIM, phTh, phTl, sP, CIDIM, CIDIM,
        scores, nullptr, nullptr, sS, NDIM, nullptr, nullptr, 0);

    // 4) softmax rows -> P hi/lo bf16 in place
    softmax_k<<<BATCH * NDIM, 256>>>(scores);

    // 5) aggregation: midT[n][ci] = P[n,:] . g[ci,:]                (M=4096, N=128, K=4096)
    __nv_bfloat16* Ph = (__nv_bfloat16*)scores;   // row stride 8192 bf16 elems
    __nv_bfloat16* Pl = Ph + NDIM;
    mma_gemm<3><<<dim3(1, 32, BATCH), blk, SM>>>(
        Ph, Pl, (long)NDIM * 2 * NDIM, 2 * NDIM, gvh, gvl, sG, NDIM, NDIM,
        nullptr, mTh, mTl, sP, CIDIM, nullptr, nullptr, 0);

    // 6) final: out[c][n] = OW[c,:] . midT[n,:] + out_b[c] + x[c][n]  (M=256, N=4096, K=128)
    mma_gemm<4><<<dim3(32, 2, BATCH), blk, SM>>>(
        OWh, OWl, 0, CIDIM, mTh, mTl, sP, CIDIM, CIDIM,
        out, nullptr, nullptr, sX, NDIM, out_b, x, sX);
}